// round 11
// baseline (speedup 1.0000x reference)
#include <cuda_runtime.h>
#include <cuda_fp16.h>
#include <cstdint>

// Problem constants (fixed shapes for SparseLinear_40278203302401)
#define BATCH 32
#define NNODES 100000
#define MNODES 100000
#define NNZ_TOTAL 3200000

// Scratch: x transposed to (N, B) in fp16 (6.4 MB) and fp32 accumulator
// in (M, B) layout (12.8 MB). Both L2 resident.
__device__ __half g_xt_h[NNODES * BATCH];
__device__ float  g_yt[MNODES * BATCH];

__device__ __forceinline__ void red_add_v4(float* addr, float4 c) {
    asm volatile("red.global.add.v4.f32 [%0], {%1, %2, %3, %4};"
                 :: "l"(addr), "f"(c.x), "f"(c.y), "f"(c.z), "f"(c.w)
                 : "memory");
}

// -------------------------------------------------------------------------
// Kernel 1: transpose x (B=32, N) -> xt_h (N, 32) fp16.
// 2 tiles (64 n-columns) per 256-thread block for 2x MLP.
// -------------------------------------------------------------------------
#define P_BLOCKS ((NNODES + 63) / 64)   // 1563 (last block: 1 tile)

__global__ void __launch_bounds__(256)
k_prep(const float* __restrict__ x, __half* __restrict__ xt) {
    __shared__ float tile[2][32][33];
    const int t  = threadIdx.x;
    const int r  = t >> 3;        // 0..31
    const int c4 = t & 7;         // 0..7
    const int n0 = blockIdx.x * 64;
    const int n1 = n0 + 32;
    const bool two = (n1 < NNODES);

    // both tile loads issued back-to-back (2x MLP)
    float4 v0 = *(const float4*)&x[r * NNODES + n0 + c4 * 4];
    float4 v1 = two ? *(const float4*)&x[r * NNODES + n1 + c4 * 4]
                    : make_float4(0.f, 0.f, 0.f, 0.f);

    tile[0][r][c4 * 4 + 0] = v0.x;  tile[0][r][c4 * 4 + 1] = v0.y;
    tile[0][r][c4 * 4 + 2] = v0.z;  tile[0][r][c4 * 4 + 3] = v0.w;
    tile[1][r][c4 * 4 + 0] = v1.x;  tile[1][r][c4 * 4 + 1] = v1.y;
    tile[1][r][c4 * 4 + 2] = v1.z;  tile[1][r][c4 * 4 + 3] = v1.w;
    __syncthreads();

    // r = n_local, c4 = batch-quad; pack 4 halves -> one 8B store per tile
    __half2 a0 = __float22half2_rn(
        make_float2(tile[0][c4 * 4 + 0][r], tile[0][c4 * 4 + 1][r]));
    __half2 a1 = __float22half2_rn(
        make_float2(tile[0][c4 * 4 + 2][r], tile[0][c4 * 4 + 3][r]));
    *(__half2*)&xt[(n0 + r) * BATCH + c4 * 4 + 0] = a0;
    *(__half2*)&xt[(n0 + r) * BATCH + c4 * 4 + 2] = a1;

    if (two) {
        __half2 b0 = __float22half2_rn(
            make_float2(tile[1][c4 * 4 + 0][r], tile[1][c4 * 4 + 1][r]));
        __half2 b1 = __float22half2_rn(
            make_float2(tile[1][c4 * 4 + 2][r], tile[1][c4 * 4 + 3][r]));
        *(__half2*)&xt[(n1 + r) * BATCH + c4 * 4 + 0] = b0;
        *(__half2*)&xt[(n1 + r) * BATCH + c4 * 4 + 2] = b1;
    }
}

// -------------------------------------------------------------------------
// Kernel 2: edge scatter. 8 lanes per edge; ONE 8B fp16 gather per lane,
// fp32 math, red.v4.f32 scatter (128B/edge).
// Each warp owns 32 consecutive edges; 4 edges in flight per iteration.
// -------------------------------------------------------------------------
__global__ void __launch_bounds__(256)
k_edges(const int* __restrict__ src, const int* __restrict__ dst,
        const float* __restrict__ val,
        const __half* __restrict__ xt, float* yt) {
    const int warp_id = (blockIdx.x * blockDim.x + threadIdx.x) >> 5;
    const int lane = threadIdx.x & 31;
    const int e0 = warp_id * 32;
    if (e0 >= NNZ_TOTAL) return;

    // lane i holds edge e0+i's metadata (coalesced; NNZ % 32 == 0)
    const int   s = src[e0 + lane];
    const int   d = dst[e0 + lane];
    const float v = val[e0 + lane];

    const int g   = lane >> 3;   // edge-group 0..3
    const int sub = lane & 7;    // batch-quad 0..7

    #pragma unroll
    for (int j = 0; j < 8; j++) {
        const int srcLane = j * 4 + g;
        const int   sj = __shfl_sync(0xffffffffu, s, srcLane);
        const int   dj = __shfl_sync(0xffffffffu, d, srcLane);
        const float vj = __shfl_sync(0xffffffffu, v, srcLane);

        // single 8B fp16 gather: 4 halves for batches sub*4 .. sub*4+3
        const int2 raw = __ldg((const int2*)&xt[sj * BATCH + sub * 4]);
        const __half2 a0 = *reinterpret_cast<const __half2*>(&raw.x);
        const __half2 a1 = *reinterpret_cast<const __half2*>(&raw.y);
        const float2 f0 = __half22float2(a0);
        const float2 f1 = __half22float2(a1);

        float4 c;
        c.x = vj * f0.x;
        c.y = vj * f0.y;
        c.z = vj * f1.x;
        c.w = vj * f1.y;
        red_add_v4(&yt[dj * BATCH + sub * 4], c);
    }
}

// -------------------------------------------------------------------------
// Kernel 3: transpose y_t (M, 32) -> out (B=32, M), + bias (folded here).
// 2 tiles (64 m-columns) per 256-thread block.
// -------------------------------------------------------------------------
#define W_BLOCKS ((MNODES + 63) / 64)   // 1563

__global__ void __launch_bounds__(256)
k_write_out(const float* __restrict__ yt, const float* __restrict__ bias,
            float* __restrict__ out) {
    __shared__ float tile[2][32][33];
    const int t  = threadIdx.x;
    const int r  = t >> 3;        // 0..31
    const int c4 = t & 7;         // 0..7
    const int m0 = blockIdx.x * 64;
    const int m1 = m0 + 32;
    const bool two = (m1 < MNODES);

    float4 v0 = *(const float4*)&yt[(m0 + r) * BATCH + c4 * 4];
    float4 v1 = two ? *(const float4*)&yt[(m1 + r) * BATCH + c4 * 4]
                    : make_float4(0.f, 0.f, 0.f, 0.f);

    // tile[k][b][m_local]
    tile[0][c4 * 4 + 0][r] = v0.x;  tile[0][c4 * 4 + 1][r] = v0.y;
    tile[0][c4 * 4 + 2][r] = v0.z;  tile[0][c4 * 4 + 3][r] = v0.w;
    tile[1][c4 * 4 + 0][r] = v1.x;  tile[1][c4 * 4 + 1][r] = v1.y;
    tile[1][c4 * 4 + 2][r] = v1.z;  tile[1][c4 * 4 + 3][r] = v1.w;
    __syncthreads();

    // r = batch, c4 = m-quad; add bias on the way out
    const float4 bb0 = *(const float4*)&bias[m0 + c4 * 4];
    float4 o0;
    o0.x = tile[0][r][c4 * 4 + 0] + bb0.x;
    o0.y = tile[0][r][c4 * 4 + 1] + bb0.y;
    o0.z = tile[0][r][c4 * 4 + 2] + bb0.z;
    o0.w = tile[0][r][c4 * 4 + 3] + bb0.w;
    *(float4*)&out[r * MNODES + m0 + c4 * 4] = o0;

    if (two) {
        const float4 bb1 = *(const float4*)&bias[m1 + c4 * 4];
        float4 o1;
        o1.x = tile[1][r][c4 * 4 + 0] + bb1.x;
        o1.y = tile[1][r][c4 * 4 + 1] + bb1.y;
        o1.z = tile[1][r][c4 * 4 + 2] + bb1.z;
        o1.w = tile[1][r][c4 * 4 + 3] + bb1.w;
        *(float4*)&out[r * MNODES + m1 + c4 * 4] = o1;
    }
}

// -------------------------------------------------------------------------
// Launch
// Inputs (metadata order): x (B*N f32), indices (2*NNZ i32), values (NNZ f32),
//                          bias (M f32). Output: (B, M) f32.
// -------------------------------------------------------------------------
extern "C" void kernel_launch(void* const* d_in, const int* in_sizes, int n_in,
                              void* d_out, int out_size) {
    const float* x      = (const float*)d_in[0];
    const int*   indices= (const int*)d_in[1];
    const float* values = (const float*)d_in[2];
    const float* bias   = (const float*)d_in[3];
    float* out = (float*)d_out;

    const int* src = indices;              // row 0
    const int* dst = indices + NNZ_TOTAL;  // row 1

    __half* xt; cudaGetSymbolAddress((void**)&xt, g_xt_h);
    float*  yt; cudaGetSymbolAddress((void**)&yt, g_yt);

    // 1a. zero accumulator (memset node — graph-capturable, driver-optimized)
    cudaMemsetAsync(yt, 0, (size_t)MNODES * BATCH * sizeof(float));

    // 1b. transpose x -> fp16 xt (2 tiles per block)
    k_prep<<<P_BLOCKS, 256>>>(x, xt);

    // 2. edge scatter: NNZ/32 warps, 8 warps per block
    const int n_warps = NNZ_TOTAL / 32;
    k_edges<<<(n_warps + 7) / 8, 256>>>(src, dst, values, xt, yt);

    // 3. transposed output + bias
    k_write_out<<<W_BLOCKS, 256>>>(yt, bias, out);
}

// round 12
// speedup vs baseline: 1.0148x; 1.0148x over previous
#include <cuda_runtime.h>
#include <cuda_fp16.h>
#include <cstdint>

// Problem constants (fixed shapes for SparseLinear_40278203302401)
#define BATCH 32
#define NNODES 100000
#define MNODES 100000
#define NNZ_TOTAL 3200000
#define NTILES 3125            // N/32 == M/32

// Scratch: x transposed to (N, B) in fp16 (6.4 MB) and fp32 accumulator
// in (M, B) layout (12.8 MB). Both L2 resident.
__device__ __half g_xt_h[NNODES * BATCH];
__device__ float  g_yt[MNODES * BATCH];

__device__ __forceinline__ void red_add_v4(float* addr, float4 c) {
    asm volatile("red.global.add.v4.f32 [%0], {%1, %2, %3, %4};"
                 :: "l"(addr), "f"(c.x), "f"(c.y), "f"(c.z), "f"(c.w)
                 : "memory");
}

// -------------------------------------------------------------------------
// Kernel 1 (role-split):
//   blocks [0, PT_BLOCKS)            : transpose x -> xt fp16, 4 tiles/block
//   blocks [PT_BLOCKS, +Z_BLOCKS)    : zero yt (4 float4 stores per thread)
// -------------------------------------------------------------------------
#define PT_BLOCKS ((NTILES + 3) / 4)               // 782
#define YT_F4     (MNODES * BATCH / 4)             // 800000 float4s
#define Z_BLOCKS  ((YT_F4 + 1023) / 1024)          // 782

__global__ void __launch_bounds__(256)
k_prep(const float* __restrict__ x, __half* __restrict__ xt,
       float4* __restrict__ yt4) {
    if (blockIdx.x < PT_BLOCKS) {
        __shared__ float tile[4][32][33];
        const int t  = threadIdx.x;
        const int r  = t >> 3;        // 0..31
        const int c4 = t & 7;         // 0..7
        const int t0 = blockIdx.x * 4;
        const int nt = min(4, NTILES - t0);

        // batch all loads first (MLP = 4)
        float4 v[4];
        #pragma unroll
        for (int k = 0; k < 4; k++) {
            if (k < nt)
                v[k] = *(const float4*)&x[r * NNODES + (t0 + k) * 32 + c4 * 4];
        }
        #pragma unroll
        for (int k = 0; k < 4; k++) {
            if (k < nt) {
                tile[k][r][c4 * 4 + 0] = v[k].x;
                tile[k][r][c4 * 4 + 1] = v[k].y;
                tile[k][r][c4 * 4 + 2] = v[k].z;
                tile[k][r][c4 * 4 + 3] = v[k].w;
            }
        }
        __syncthreads();

        // r = n_local, c4 = batch-quad; 4 halves -> one 8B store per tile
        #pragma unroll
        for (int k = 0; k < 4; k++) {
            if (k < nt) {
                __half2 h0 = __float22half2_rn(
                    make_float2(tile[k][c4 * 4 + 0][r], tile[k][c4 * 4 + 1][r]));
                __half2 h1 = __float22half2_rn(
                    make_float2(tile[k][c4 * 4 + 2][r], tile[k][c4 * 4 + 3][r]));
                uint2 p;
                p.x = *reinterpret_cast<unsigned*>(&h0);
                p.y = *reinterpret_cast<unsigned*>(&h1);
                *(uint2*)&xt[((t0 + k) * 32 + r) * BATCH + c4 * 4] = p;
            }
        }
    } else {
        // ---- zero yt: 4 float4 stores per thread ----
        const int base = (blockIdx.x - PT_BLOCKS) * 1024 + threadIdx.x;
        const float4 z = make_float4(0.f, 0.f, 0.f, 0.f);
        #pragma unroll
        for (int k = 0; k < 4; k++) {
            const int idx = base + k * 256;
            if (idx < YT_F4) yt4[idx] = z;
        }
    }
}

// -------------------------------------------------------------------------
// Kernel 2: edge scatter. 8 lanes per edge; one 8B fp16 gather per lane,
// fp32 math, red.v4.f32 scatter (128B/edge). At the LTS byte floor.
// -------------------------------------------------------------------------
__global__ void __launch_bounds__(256)
k_edges(const int* __restrict__ src, const int* __restrict__ dst,
        const float* __restrict__ val,
        const __half* __restrict__ xt, float* yt) {
    const int warp_id = (blockIdx.x * blockDim.x + threadIdx.x) >> 5;
    const int lane = threadIdx.x & 31;
    const int e0 = warp_id * 32;
    if (e0 >= NNZ_TOTAL) return;

    const int   s = src[e0 + lane];
    const int   d = dst[e0 + lane];
    const float v = val[e0 + lane];

    const int g   = lane >> 3;   // edge-group 0..3
    const int sub = lane & 7;    // batch-quad 0..7

    #pragma unroll
    for (int j = 0; j < 8; j++) {
        const int srcLane = j * 4 + g;
        const int   sj = __shfl_sync(0xffffffffu, s, srcLane);
        const int   dj = __shfl_sync(0xffffffffu, d, srcLane);
        const float vj = __shfl_sync(0xffffffffu, v, srcLane);

        const int2 raw = __ldg((const int2*)&xt[sj * BATCH + sub * 4]);
        const __half2 a0 = *reinterpret_cast<const __half2*>(&raw.x);
        const __half2 a1 = *reinterpret_cast<const __half2*>(&raw.y);
        const float2 f0 = __half22float2(a0);
        const float2 f1 = __half22float2(a1);

        float4 c;
        c.x = vj * f0.x;
        c.y = vj * f0.y;
        c.z = vj * f1.x;
        c.w = vj * f1.y;
        red_add_v4(&yt[dj * BATCH + sub * 4], c);
    }
}

// -------------------------------------------------------------------------
// Kernel 3: transpose y_t (M, 32) -> out (B=32, M) + bias, 4 tiles/block.
// -------------------------------------------------------------------------
#define W_BLOCKS ((NTILES + 3) / 4)   // 782

__global__ void __launch_bounds__(256)
k_write_out(const float* __restrict__ yt, const float* __restrict__ bias,
            float* __restrict__ out) {
    __shared__ float tile[4][32][33];
    const int t  = threadIdx.x;
    const int r  = t >> 3;        // 0..31
    const int c4 = t & 7;         // 0..7
    const int t0 = blockIdx.x * 4;
    const int nt = min(4, NTILES - t0);

    // batch all loads first (MLP = 4)
    float4 v[4];
    #pragma unroll
    for (int k = 0; k < 4; k++) {
        if (k < nt)
            v[k] = *(const float4*)&yt[((t0 + k) * 32 + r) * BATCH + c4 * 4];
    }
    #pragma unroll
    for (int k = 0; k < 4; k++) {
        if (k < nt) {
            tile[k][c4 * 4 + 0][r] = v[k].x;   // tile[k][b][m_local]
            tile[k][c4 * 4 + 1][r] = v[k].y;
            tile[k][c4 * 4 + 2][r] = v[k].z;
            tile[k][c4 * 4 + 3][r] = v[k].w;
        }
    }
    __syncthreads();

    // r = batch, c4 = m-quad; add bias on the way out
    #pragma unroll
    for (int k = 0; k < 4; k++) {
        if (k < nt) {
            const int m = (t0 + k) * 32;
            const float4 bb = *(const float4*)&bias[m + c4 * 4];
            float4 o;
            o.x = tile[k][r][c4 * 4 + 0] + bb.x;
            o.y = tile[k][r][c4 * 4 + 1] + bb.y;
            o.z = tile[k][r][c4 * 4 + 2] + bb.z;
            o.w = tile[k][r][c4 * 4 + 3] + bb.w;
            *(float4*)&out[r * MNODES + m + c4 * 4] = o;
        }
    }
}

// -------------------------------------------------------------------------
// Launch
// Inputs (metadata order): x (B*N f32), indices (2*NNZ i32), values (NNZ f32),
//                          bias (M f32). Output: (B, M) f32.
// -------------------------------------------------------------------------
extern "C" void kernel_launch(void* const* d_in, const int* in_sizes, int n_in,
                              void* d_out, int out_size) {
    const float* x      = (const float*)d_in[0];
    const int*   indices= (const int*)d_in[1];
    const float* values = (const float*)d_in[2];
    const float* bias   = (const float*)d_in[3];
    float* out = (float*)d_out;

    const int* src = indices;              // row 0
    const int* dst = indices + NNZ_TOTAL;  // row 1

    __half* xt; cudaGetSymbolAddress((void**)&xt, g_xt_h);
    float*  yt; cudaGetSymbolAddress((void**)&yt, g_yt);

    // 1. fused: transpose x -> fp16 xt  +  zero yt (role-split blocks)
    k_prep<<<PT_BLOCKS + Z_BLOCKS, 256>>>(x, xt, (float4*)yt);

    // 2. edge scatter: NNZ/32 warps, 8 warps per block
    const int n_warps = NNZ_TOTAL / 32;
    k_edges<<<(n_warps + 7) / 8, 256>>>(src, dst, values, xt, yt);

    // 3. transposed output + bias (4 tiles per block)
    k_write_out<<<W_BLOCKS, 256>>>(yt, bias, out);
}